// round 1
// baseline (speedup 1.0000x reference)
#include <cuda_runtime.h>

// Problem constants
#define NN_ 2048
#define BB_ 16
#define DD_ 8
static __device__ __constant__ const float kAlpha = 0.95122945f;   // ALPHA_P == ALPHA_D
static __device__ __constant__ const float kOneMinusAlpha = 1.0f - 0.95122945f;

// ---------------------------------------------------------------------------
// Main kernel: one block = (fixed e, 1024-wide o tile). 256 threads x float4.
// Loops all 16 b internally so dmap/A_p/A_d (no b dependence) are read once.
// ---------------------------------------------------------------------------
__global__ void __launch_bounds__(256, 4) stdp_main(
    const float* __restrict__ Xd,        // [D,B,N]
    const float* __restrict__ Xpost,     // [B,N]
    const float* __restrict__ xbar_pre,  // [D,B,N]
    const float* __restrict__ xbar_post, // [B,N]
    const float* __restrict__ W,         // [B,N,N] (b,e,o)
    const float* __restrict__ A_p,       // [N,N]   (e,o)
    const float* __restrict__ A_d,       // [N,N]   (e,o)
    const float* __restrict__ dmap,      // [D,N,N] (d,e,o)
    float* __restrict__ out,             // [B,N,N]
    float* __restrict__ Wnew)            // [B,N,N]
{
    const int e = blockIdx.y;
    const int o = (blockIdx.x * 256 + threadIdx.x) * 4;

    // Per-(e) scalars shared across the whole block
    __shared__ float s_pre[DD_][BB_];
    __shared__ float s_xd [DD_][BB_];
    {
        const int t = threadIdx.x;
        if (t < DD_ * BB_) {
            const int d = t >> 4, b = t & 15;
            s_pre[d][b] = xbar_pre[((size_t)d * BB_ + b) * NN_ + e];
        } else if (t < 2 * DD_ * BB_) {
            const int i = t - DD_ * BB_;
            const int d = i >> 4, b = i & 15;
            s_xd[d][b] = Xd[((size_t)d * BB_ + b) * NN_ + e];
        }
    }
    __syncthreads();

    const size_t eo = (size_t)e * NN_ + o;

    // Load dmap planes + A_p/A_d once (b-invariant)
    float4 dm[DD_];
#pragma unroll
    for (int d = 0; d < DD_; d++)
        dm[d] = *reinterpret_cast<const float4*>(dmap + (size_t)d * NN_ * NN_ + eo);
    const float4 ap = *reinterpret_cast<const float4*>(A_p + eo);
    const float4 ad = *reinterpret_cast<const float4*>(A_d + eo);

#pragma unroll 4
    for (int b = 0; b < BB_; b++) {
        float4 pot = make_float4(0.f, 0.f, 0.f, 0.f);
        float4 dep = make_float4(0.f, 0.f, 0.f, 0.f);
#pragma unroll
        for (int d = 0; d < DD_; d++) {
            const float p = s_pre[d][b];
            pot.x = fmaf(dm[d].x, p, pot.x);
            pot.y = fmaf(dm[d].y, p, pot.y);
            pot.z = fmaf(dm[d].z, p, pot.z);
            pot.w = fmaf(dm[d].w, p, pot.w);
            const float q = s_xd[d][b];
            dep.x = fmaf(dm[d].x, q, dep.x);
            dep.y = fmaf(dm[d].y, q, dep.y);
            dep.z = fmaf(dm[d].z, q, dep.z);
            dep.w = fmaf(dm[d].w, q, dep.w);
        }

        const float4 xp = *reinterpret_cast<const float4*>(Xpost     + (size_t)b * NN_ + o);
        const float4 xb = *reinterpret_cast<const float4*>(xbar_post + (size_t)b * NN_ + o);

        const size_t idx = (size_t)b * NN_ * NN_ + eo;
        const float4 w = *reinterpret_cast<const float4*>(W + idx);
        *reinterpret_cast<float4*>(out + idx) = w;   // out = W (pre-update copy)

        float4 wn;
        wn.x = fminf(fmaxf(fmaf(xp.x * ap.x, pot.x, fmaf(-xb.x * ad.x, dep.x, w.x)), 0.f), 1.f);
        wn.y = fminf(fmaxf(fmaf(xp.y * ap.y, pot.y, fmaf(-xb.y * ad.y, dep.y, w.y)), 0.f), 1.f);
        wn.z = fminf(fmaxf(fmaf(xp.z * ap.z, pot.z, fmaf(-xb.z * ad.z, dep.z, w.z)), 0.f), 1.f);
        wn.w = fminf(fmaxf(fmaf(xp.w * ap.w, pot.w, fmaf(-xb.w * ad.w, dep.w, w.w)), 0.f), 1.f);
        *reinterpret_cast<float4*>(Wnew + idx) = wn;
    }
}

// ---------------------------------------------------------------------------
// Trace-update epilogue (tiny, ~3 MB total traffic)
// xbar_new = alpha * xbar + (1-alpha) * x
// ---------------------------------------------------------------------------
__global__ void trace_update(
    const float4* __restrict__ Xd,        // D*B*N/4
    const float4* __restrict__ Xpost,     // B*N/4
    const float4* __restrict__ xbar_pre,
    const float4* __restrict__ xbar_post,
    float4* __restrict__ pre_out,
    float4* __restrict__ post_out)
{
    const int npre  = DD_ * BB_ * NN_ / 4;   // 65536
    const int npost = BB_ * NN_ / 4;         //  8192
    const int i = blockIdx.x * blockDim.x + threadIdx.x;
    if (i < npre) {
        const float4 x  = Xd[i];
        const float4 xb = xbar_pre[i];
        float4 r;
        r.x = fmaf(kAlpha, xb.x, kOneMinusAlpha * x.x);
        r.y = fmaf(kAlpha, xb.y, kOneMinusAlpha * x.y);
        r.z = fmaf(kAlpha, xb.z, kOneMinusAlpha * x.z);
        r.w = fmaf(kAlpha, xb.w, kOneMinusAlpha * x.w);
        pre_out[i] = r;
    } else if (i < npre + npost) {
        const int j = i - npre;
        const float4 x  = Xpost[j];
        const float4 xb = xbar_post[j];
        float4 r;
        r.x = fmaf(kAlpha, xb.x, kOneMinusAlpha * x.x);
        r.y = fmaf(kAlpha, xb.y, kOneMinusAlpha * x.y);
        r.z = fmaf(kAlpha, xb.z, kOneMinusAlpha * x.z);
        r.w = fmaf(kAlpha, xb.w, kOneMinusAlpha * x.w);
        post_out[j] = r;
    }
}

extern "C" void kernel_launch(void* const* d_in, const int* in_sizes, int n_in,
                              void* d_out, int out_size)
{
    // Inputs in setup_inputs() order:
    const float* Xd        = (const float*)d_in[0]; // (D,B,N)
    const float* Xpost     = (const float*)d_in[1]; // (B,N)
    const float* xbar_pre  = (const float*)d_in[2]; // (D,B,N)
    const float* xbar_post = (const float*)d_in[3]; // (B,N)
    const float* W         = (const float*)d_in[4]; // (B,N,N)
    const float* A_p       = (const float*)d_in[5]; // (N,N)
    const float* A_d       = (const float*)d_in[6]; // (N,N)
    const float* dmap      = (const float*)d_in[7]; // (D,N,N)

    // Outputs concatenated in reference return order:
    float* out      = (float*)d_out;
    float* Wnew     = out  + (size_t)BB_ * NN_ * NN_;
    float* pre_out  = Wnew + (size_t)BB_ * NN_ * NN_;
    float* post_out = pre_out + (size_t)DD_ * BB_ * NN_;

    dim3 grid(NN_ / (256 * 4), NN_);  // (2, 2048)
    stdp_main<<<grid, 256>>>(Xd, Xpost, xbar_pre, xbar_post, W, A_p, A_d, dmap,
                             out, Wnew);

    const int ntot = (DD_ * BB_ * NN_ + BB_ * NN_) / 4;  // 73728
    trace_update<<<(ntot + 255) / 256, 256>>>(
        (const float4*)Xd, (const float4*)Xpost,
        (const float4*)xbar_pre, (const float4*)xbar_post,
        (float4*)pre_out, (float4*)post_out);
}

// round 2
// speedup vs baseline: 2.1001x; 2.1001x over previous
#include <cuda_runtime.h>

// Problem constants
#define NN_ 2048
#define BB_ 16
#define DD_ 8
static __device__ __constant__ const float kAlpha = 0.95122945f;   // ALPHA_P == ALPHA_D
static __device__ __constant__ const float kOneMinusAlpha = 1.0f - 0.95122945f;

// ---------------------------------------------------------------------------
// Main kernel: one block = (fixed e, 1024-wide o tile). 256 threads x float4.
// Loops all 16 b internally so dmap/A_p/A_d (no b dependence) are read once.
// NO occupancy forcing: must avoid register spills (dm[8] = 32 regs live
// across whole b-loop). Unroll 2 keeps live set bounded while giving ~6
// outstanding LDG.128 per warp for latency hiding.
// ---------------------------------------------------------------------------
__global__ void __launch_bounds__(256) stdp_main(
    const float* __restrict__ Xd,        // [D,B,N]
    const float* __restrict__ Xpost,     // [B,N]
    const float* __restrict__ xbar_pre,  // [D,B,N]
    const float* __restrict__ xbar_post, // [B,N]
    const float* __restrict__ W,         // [B,N,N] (b,e,o)
    const float* __restrict__ A_p,       // [N,N]   (e,o)
    const float* __restrict__ A_d,       // [N,N]   (e,o)
    const float* __restrict__ dmap,      // [D,N,N] (d,e,o)
    float* __restrict__ out,             // [B,N,N]
    float* __restrict__ Wnew)            // [B,N,N]
{
    const int e = blockIdx.y;
    const int o = (blockIdx.x * 256 + threadIdx.x) * 4;

    // Per-(e) scalars shared across the whole block
    __shared__ float s_pre[DD_][BB_];
    __shared__ float s_xd [DD_][BB_];
    {
        const int t = threadIdx.x;
        if (t < DD_ * BB_) {
            const int d = t >> 4, b = t & 15;
            s_pre[d][b] = xbar_pre[((size_t)d * BB_ + b) * NN_ + e];
        } else if (t < 2 * DD_ * BB_) {
            const int i = t - DD_ * BB_;
            const int d = i >> 4, b = i & 15;
            s_xd[d][b] = Xd[((size_t)d * BB_ + b) * NN_ + e];
        }
    }
    __syncthreads();

    const size_t eo = (size_t)e * NN_ + o;

    // Load dmap planes + A_p/A_d once (b-invariant). Streaming: zero reuse
    // across blocks -> evict-first so L2 keeps the small reused vectors.
    float4 dm[DD_];
#pragma unroll
    for (int d = 0; d < DD_; d++)
        dm[d] = __ldcs(reinterpret_cast<const float4*>(dmap + (size_t)d * NN_ * NN_ + eo));
    const float4 ap = __ldcs(reinterpret_cast<const float4*>(A_p + eo));
    const float4 ad = __ldcs(reinterpret_cast<const float4*>(A_d + eo));

#pragma unroll 2
    for (int b = 0; b < BB_; b++) {
        float4 pot = make_float4(0.f, 0.f, 0.f, 0.f);
        float4 dep = make_float4(0.f, 0.f, 0.f, 0.f);
#pragma unroll
        for (int d = 0; d < DD_; d++) {
            const float p = s_pre[d][b];
            pot.x = fmaf(dm[d].x, p, pot.x);
            pot.y = fmaf(dm[d].y, p, pot.y);
            pot.z = fmaf(dm[d].z, p, pot.z);
            pot.w = fmaf(dm[d].w, p, pot.w);
            const float q = s_xd[d][b];
            dep.x = fmaf(dm[d].x, q, dep.x);
            dep.y = fmaf(dm[d].y, q, dep.y);
            dep.z = fmaf(dm[d].z, q, dep.z);
            dep.w = fmaf(dm[d].w, q, dep.w);
        }

        // Xpost/xbar_post rows are reused by all 2048 e-blocks: default
        // (caching) loads keep them L2-resident.
        const float4 xp = *reinterpret_cast<const float4*>(Xpost     + (size_t)b * NN_ + o);
        const float4 xb = *reinterpret_cast<const float4*>(xbar_post + (size_t)b * NN_ + o);

        const size_t idx = (size_t)b * NN_ * NN_ + eo;
        const float4 w = __ldcs(reinterpret_cast<const float4*>(W + idx));
        __stcs(reinterpret_cast<float4*>(out + idx), w);   // out = W (pre-update copy)

        float4 wn;
        wn.x = fminf(fmaxf(fmaf(xp.x * ap.x, pot.x, fmaf(-xb.x * ad.x, dep.x, w.x)), 0.f), 1.f);
        wn.y = fminf(fmaxf(fmaf(xp.y * ap.y, pot.y, fmaf(-xb.y * ad.y, dep.y, w.y)), 0.f), 1.f);
        wn.z = fminf(fmaxf(fmaf(xp.z * ap.z, pot.z, fmaf(-xb.z * ad.z, dep.z, w.z)), 0.f), 1.f);
        wn.w = fminf(fmaxf(fmaf(xp.w * ap.w, pot.w, fmaf(-xb.w * ad.w, dep.w, w.w)), 0.f), 1.f);
        __stcs(reinterpret_cast<float4*>(Wnew + idx), wn);
    }
}

// ---------------------------------------------------------------------------
// Trace-update epilogue (tiny, ~3 MB total traffic)
// xbar_new = alpha * xbar + (1-alpha) * x
// ---------------------------------------------------------------------------
__global__ void trace_update(
    const float4* __restrict__ Xd,        // D*B*N/4
    const float4* __restrict__ Xpost,     // B*N/4
    const float4* __restrict__ xbar_pre,
    const float4* __restrict__ xbar_post,
    float4* __restrict__ pre_out,
    float4* __restrict__ post_out)
{
    const int npre  = DD_ * BB_ * NN_ / 4;   // 65536
    const int npost = BB_ * NN_ / 4;         //  8192
    const int i = blockIdx.x * blockDim.x + threadIdx.x;
    if (i < npre) {
        const float4 x  = Xd[i];
        const float4 xb = xbar_pre[i];
        float4 r;
        r.x = fmaf(kAlpha, xb.x, kOneMinusAlpha * x.x);
        r.y = fmaf(kAlpha, xb.y, kOneMinusAlpha * x.y);
        r.z = fmaf(kAlpha, xb.z, kOneMinusAlpha * x.z);
        r.w = fmaf(kAlpha, xb.w, kOneMinusAlpha * x.w);
        pre_out[i] = r;
    } else if (i < npre + npost) {
        const int j = i - npre;
        const float4 x  = Xpost[j];
        const float4 xb = xbar_post[j];
        float4 r;
        r.x = fmaf(kAlpha, xb.x, kOneMinusAlpha * x.x);
        r.y = fmaf(kAlpha, xb.y, kOneMinusAlpha * x.y);
        r.z = fmaf(kAlpha, xb.z, kOneMinusAlpha * x.z);
        r.w = fmaf(kAlpha, xb.w, kOneMinusAlpha * x.w);
        post_out[j] = r;
    }
}

extern "C" void kernel_launch(void* const* d_in, const int* in_sizes, int n_in,
                              void* d_out, int out_size)
{
    // Inputs in setup_inputs() order:
    const float* Xd        = (const float*)d_in[0]; // (D,B,N)
    const float* Xpost     = (const float*)d_in[1]; // (B,N)
    const float* xbar_pre  = (const float*)d_in[2]; // (D,B,N)
    const float* xbar_post = (const float*)d_in[3]; // (B,N)
    const float* W         = (const float*)d_in[4]; // (B,N,N)
    const float* A_p       = (const float*)d_in[5]; // (N,N)
    const float* A_d       = (const float*)d_in[6]; // (N,N)
    const float* dmap      = (const float*)d_in[7]; // (D,N,N)

    // Outputs concatenated in reference return order:
    float* out      = (float*)d_out;
    float* Wnew     = out  + (size_t)BB_ * NN_ * NN_;
    float* pre_out  = Wnew + (size_t)BB_ * NN_ * NN_;
    float* post_out = pre_out + (size_t)DD_ * BB_ * NN_;

    dim3 grid(NN_ / (256 * 4), NN_);  // (2, 2048)
    stdp_main<<<grid, 256>>>(Xd, Xpost, xbar_pre, xbar_post, W, A_p, A_d, dmap,
                             out, Wnew);

    const int ntot = (DD_ * BB_ * NN_ + BB_ * NN_) / 4;  // 73728
    trace_update<<<(ntot + 255) / 256, 256>>>(
        (const float4*)Xd, (const float4*)Xpost,
        (const float4*)xbar_pre, (const float4*)xbar_post,
        (float4*)pre_out, (float4*)post_out);
}

// round 3
// speedup vs baseline: 2.4107x; 1.1479x over previous
#include <cuda_runtime.h>

// Problem constants
#define NN_ 2048
#define BB_ 16
#define DD_ 8
#define TRACE_BLKS 32                      // extra virtual blocks for trace update

static __device__ __constant__ const float kAlpha = 0.95122945f;   // ALPHA_P == ALPHA_D
static __device__ __constant__ const float kOneMinusAlpha = 1.0f - 0.95122945f;

// ---------------------------------------------------------------------------
// Fused kernel.
//   blockIdx.y <  NN_ : main STDP update. One block = (fixed e, 1024-wide o
//                       tile), 256 threads x float4, loops all 16 b with
//                       batched-4 W prefetch (software pipeline) for MLP.
//   blockIdx.y >= NN_ : trace-update stream (xbar expfilt), 32 virtual blocks.
// ---------------------------------------------------------------------------
__global__ void __launch_bounds__(256) stdp_fused(
    const float* __restrict__ Xd,        // [D,B,N]
    const float* __restrict__ Xpost,     // [B,N]
    const float* __restrict__ xbar_pre,  // [D,B,N]
    const float* __restrict__ xbar_post, // [B,N]
    const float* __restrict__ W,         // [B,N,N] (b,e,o)
    const float* __restrict__ A_p,       // [N,N]   (e,o)
    const float* __restrict__ A_d,       // [N,N]   (e,o)
    const float* __restrict__ dmap,      // [D,N,N] (d,e,o)
    float* __restrict__ out,             // [B,N,N]
    float* __restrict__ Wnew,            // [B,N,N]
    float* __restrict__ pre_out,         // [D,B,N]
    float* __restrict__ post_out)        // [B,N]
{
    if (blockIdx.y >= NN_) {
        // ---- trace-update tail: tiny elementwise stream (~3MB) ----
        const int vb = (blockIdx.y - NN_) * gridDim.x + blockIdx.x;   // 0..31
        const int tg = vb * 256 + threadIdx.x;                        // 0..8191
        const int npre  = DD_ * BB_ * NN_ / 4;   // 65536
        const int ntot  = npre + BB_ * NN_ / 4;  // 73728
        for (int i = tg; i < ntot; i += TRACE_BLKS * 256) {
            float4 x, xb;
            if (i < npre) {
                x  = reinterpret_cast<const float4*>(Xd)[i];
                xb = reinterpret_cast<const float4*>(xbar_pre)[i];
            } else {
                x  = reinterpret_cast<const float4*>(Xpost)[i - npre];
                xb = reinterpret_cast<const float4*>(xbar_post)[i - npre];
            }
            float4 r;
            r.x = fmaf(kAlpha, xb.x, kOneMinusAlpha * x.x);
            r.y = fmaf(kAlpha, xb.y, kOneMinusAlpha * x.y);
            r.z = fmaf(kAlpha, xb.z, kOneMinusAlpha * x.z);
            r.w = fmaf(kAlpha, xb.w, kOneMinusAlpha * x.w);
            if (i < npre) reinterpret_cast<float4*>(pre_out)[i] = r;
            else          reinterpret_cast<float4*>(post_out)[i - npre] = r;
        }
        return;
    }

    // ---- main STDP path ----
    const int e = blockIdx.y;
    const int o = (blockIdx.x * 256 + threadIdx.x) * 4;

    // Per-(e) scalars shared across the whole block
    __shared__ float s_pre[DD_][BB_];
    __shared__ float s_xd [DD_][BB_];
    {
        const int t = threadIdx.x;
        if (t < DD_ * BB_) {
            const int d = t >> 4, b = t & 15;
            s_pre[d][b] = xbar_pre[((size_t)d * BB_ + b) * NN_ + e];
        } else if (t < 2 * DD_ * BB_) {
            const int i = t - DD_ * BB_;
            const int d = i >> 4, b = i & 15;
            s_xd[d][b] = Xd[((size_t)d * BB_ + b) * NN_ + e];
        }
    }
    __syncthreads();

    const size_t eo = (size_t)e * NN_ + o;

    // b-invariant planes, read once, streaming (no cross-block reuse).
    float4 dm[DD_];
#pragma unroll
    for (int d = 0; d < DD_; d++)
        dm[d] = __ldcs(reinterpret_cast<const float4*>(dmap + (size_t)d * NN_ * NN_ + eo));
    const float4 ap = __ldcs(reinterpret_cast<const float4*>(A_p + eo));
    const float4 ad = __ldcs(reinterpret_cast<const float4*>(A_d + eo));

    // Software-pipelined b-loop: batch-load 4 W tiles, prefetch next 4 while
    // processing, so ~8 LDG.128 stay in flight per warp.
    float4 wcur[4];
#pragma unroll
    for (int j = 0; j < 4; j++)
        wcur[j] = __ldcs(reinterpret_cast<const float4*>(W + (size_t)j * NN_ * NN_ + eo));

#pragma unroll
    for (int b0 = 0; b0 < BB_; b0 += 4) {
        float4 wnxt[4];
        if (b0 + 4 < BB_) {
#pragma unroll
            for (int j = 0; j < 4; j++)
                wnxt[j] = __ldcs(reinterpret_cast<const float4*>(
                    W + (size_t)(b0 + 4 + j) * NN_ * NN_ + eo));
        }

#pragma unroll
        for (int j = 0; j < 4; j++) {
            const int b = b0 + j;
            float4 pot = make_float4(0.f, 0.f, 0.f, 0.f);
            float4 dep = make_float4(0.f, 0.f, 0.f, 0.f);
#pragma unroll
            for (int d = 0; d < DD_; d++) {
                const float p = s_pre[d][b];
                pot.x = fmaf(dm[d].x, p, pot.x);
                pot.y = fmaf(dm[d].y, p, pot.y);
                pot.z = fmaf(dm[d].z, p, pot.z);
                pot.w = fmaf(dm[d].w, p, pot.w);
                const float q = s_xd[d][b];
                dep.x = fmaf(dm[d].x, q, dep.x);
                dep.y = fmaf(dm[d].y, q, dep.y);
                dep.z = fmaf(dm[d].z, q, dep.z);
                dep.w = fmaf(dm[d].w, q, dep.w);
            }

            // L2-resident reused rows: default caching loads.
            const float4 xp = *reinterpret_cast<const float4*>(Xpost     + (size_t)b * NN_ + o);
            const float4 xb = *reinterpret_cast<const float4*>(xbar_post + (size_t)b * NN_ + o);

            const size_t idx = (size_t)b * NN_ * NN_ + eo;
            const float4 w = wcur[j];
            __stcs(reinterpret_cast<float4*>(out + idx), w);   // out = W pre-update

            float4 wn;
            wn.x = fminf(fmaxf(fmaf(xp.x * ap.x, pot.x, fmaf(-xb.x * ad.x, dep.x, w.x)), 0.f), 1.f);
            wn.y = fminf(fmaxf(fmaf(xp.y * ap.y, pot.y, fmaf(-xb.y * ad.y, dep.y, w.y)), 0.f), 1.f);
            wn.z = fminf(fmaxf(fmaf(xp.z * ap.z, pot.z, fmaf(-xb.z * ad.z, dep.z, w.z)), 0.f), 1.f);
            wn.w = fminf(fmaxf(fmaf(xp.w * ap.w, pot.w, fmaf(-xb.w * ad.w, dep.w, w.w)), 0.f), 1.f);
            __stcs(reinterpret_cast<float4*>(Wnew + idx), wn);
        }

#pragma unroll
        for (int j = 0; j < 4; j++) wcur[j] = wnxt[j];
    }
}

extern "C" void kernel_launch(void* const* d_in, const int* in_sizes, int n_in,
                              void* d_out, int out_size)
{
    // Inputs in setup_inputs() order:
    const float* Xd        = (const float*)d_in[0]; // (D,B,N)
    const float* Xpost     = (const float*)d_in[1]; // (B,N)
    const float* xbar_pre  = (const float*)d_in[2]; // (D,B,N)
    const float* xbar_post = (const float*)d_in[3]; // (B,N)
    const float* W         = (const float*)d_in[4]; // (B,N,N)
    const float* A_p       = (const float*)d_in[5]; // (N,N)
    const float* A_d       = (const float*)d_in[6]; // (N,N)
    const float* dmap      = (const float*)d_in[7]; // (D,N,N)

    // Outputs concatenated in reference return order:
    float* out      = (float*)d_out;
    float* Wnew     = out  + (size_t)BB_ * NN_ * NN_;
    float* pre_out  = Wnew + (size_t)BB_ * NN_ * NN_;
    float* post_out = pre_out + (size_t)DD_ * BB_ * NN_;

    // grid: x=2 covers o in 1024-wide tiles; y rows [0,2048) main work,
    // y rows [2048, 2048+16) provide 32 blocks for the trace-update stream.
    dim3 grid(NN_ / (256 * 4), NN_ + TRACE_BLKS / (NN_ / (256 * 4)));
    stdp_fused<<<grid, 256>>>(Xd, Xpost, xbar_pre, xbar_post, W, A_p, A_d, dmap,
                              out, Wnew, pre_out, post_out);
}

// round 4
// speedup vs baseline: 2.8028x; 1.1627x over previous
#include <cuda_runtime.h>
#include <cstdint>

// Problem constants
#define NN_ 2048
#define BB_ 16
#define DD_ 8
#define TRACE_BLKS 32

static __device__ __constant__ const float kAlpha = 0.95122945f;
static __device__ __constant__ const float kOneMinusAlpha = 1.0f - 0.95122945f;

// Shared layout (dynamic): W stage [16][1024] floats, then s_pre[8][16], s_xd[8][16]
#define SW_FLOATS   (BB_ * 1024)          // 16384 floats = 64KB
#define SMEM_FLOATS (SW_FLOATS + 2 * DD_ * BB_)

#define CP_ASYNC16(smem_u32, gptr) \
    asm volatile("cp.async.cg.shared.global [%0], [%1], 16;" \
                 :: "r"(smem_u32), "l"(gptr) : "memory")
#define CP_COMMIT() asm volatile("cp.async.commit_group;" ::: "memory")
#define CP_WAIT(n)  asm volatile("cp.async.wait_group %0;" :: "n"(n) : "memory")

__device__ __forceinline__ uint32_t smem_u32(const void* p) {
    return (uint32_t)__cvta_generic_to_shared(p);
}

// ---------------------------------------------------------------------------
// Fused kernel.
//   blockIdx.y <  NN_ : main STDP update, cp.async-staged W pipeline.
//   blockIdx.y >= NN_ : trace-update elementwise stream (~3MB).
// ---------------------------------------------------------------------------
__global__ void __launch_bounds__(256, 2) stdp_fused(
    const float* __restrict__ Xd,        // [D,B,N]
    const float* __restrict__ Xpost,     // [B,N]
    const float* __restrict__ xbar_pre,  // [D,B,N]
    const float* __restrict__ xbar_post, // [B,N]
    const float* __restrict__ W,         // [B,N,N] (b,e,o)
    const float* __restrict__ A_p,       // [N,N]   (e,o)
    const float* __restrict__ A_d,       // [N,N]   (e,o)
    const float* __restrict__ dmap,      // [D,N,N] (d,e,o)
    float* __restrict__ out,             // [B,N,N]
    float* __restrict__ Wnew,            // [B,N,N]
    float* __restrict__ pre_out,         // [D,B,N]
    float* __restrict__ post_out)        // [B,N]
{
    extern __shared__ float sm[];
    float* s_w   = sm;                    // [16][1024]
    float* s_pre = sm + SW_FLOATS;        // [8][16]
    float* s_xd  = s_pre + DD_ * BB_;     // [8][16]

    if (blockIdx.y >= NN_) {
        // ---- trace-update tail ----
        const int vb = (blockIdx.y - NN_) * gridDim.x + blockIdx.x;   // 0..31
        const int tg = vb * 256 + threadIdx.x;
        const int npre = DD_ * BB_ * NN_ / 4;   // 65536
        const int ntot = npre + BB_ * NN_ / 4;  // 73728
        for (int i = tg; i < ntot; i += TRACE_BLKS * 256) {
            float4 x, xb;
            if (i < npre) {
                x  = reinterpret_cast<const float4*>(Xd)[i];
                xb = reinterpret_cast<const float4*>(xbar_pre)[i];
            } else {
                x  = reinterpret_cast<const float4*>(Xpost)[i - npre];
                xb = reinterpret_cast<const float4*>(xbar_post)[i - npre];
            }
            float4 r;
            r.x = fmaf(kAlpha, xb.x, kOneMinusAlpha * x.x);
            r.y = fmaf(kAlpha, xb.y, kOneMinusAlpha * x.y);
            r.z = fmaf(kAlpha, xb.z, kOneMinusAlpha * x.z);
            r.w = fmaf(kAlpha, xb.w, kOneMinusAlpha * x.w);
            if (i < npre) reinterpret_cast<float4*>(pre_out)[i] = r;
            else          reinterpret_cast<float4*>(post_out)[i - npre] = r;
        }
        return;
    }

    // ---- main STDP path ----
    const int e = blockIdx.y;
    const int t = threadIdx.x;
    const int o = blockIdx.x * 1024 + t * 4;
    const size_t eo = (size_t)e * NN_ + o;

    // Kick off async staging of all 16 W[b] tiles: 4 groups of 4.
    const uint32_t swa = smem_u32(s_w + t * 4);
#pragma unroll
    for (int g = 0; g < 4; g++) {
#pragma unroll
        for (int j = 0; j < 4; j++) {
            const int b = g * 4 + j;
            CP_ASYNC16(swa + (uint32_t)b * 4096u, W + (size_t)b * NN_ * NN_ + eo);
        }
        CP_COMMIT();
    }

    // b-invariant planes (overlap with cp.async fills).
    float4 dm[DD_];
#pragma unroll
    for (int d = 0; d < DD_; d++)
        dm[d] = __ldcs(reinterpret_cast<const float4*>(dmap + (size_t)d * NN_ * NN_ + eo));
    const float4 ap = __ldcs(reinterpret_cast<const float4*>(A_p + eo));
    const float4 ad = __ldcs(reinterpret_cast<const float4*>(A_d + eo));

    // Per-(e) scalars.
    if (t < DD_ * BB_) {
        const int d = t >> 4, b = t & 15;
        s_pre[t] = xbar_pre[((size_t)d * BB_ + b) * NN_ + e];
    } else {
        const int i = t - DD_ * BB_;
        const int d = i >> 4, b = i & 15;
        s_xd[i] = Xd[((size_t)d * BB_ + b) * NN_ + e];
    }
    __syncthreads();

#define PROCESS4(B0)                                                            \
    {                                                                           \
        _Pragma("unroll")                                                       \
        for (int j = 0; j < 4; j++) {                                           \
            const int b = (B0) + j;                                             \
            float4 pot = make_float4(0.f, 0.f, 0.f, 0.f);                       \
            float4 dep = make_float4(0.f, 0.f, 0.f, 0.f);                       \
            _Pragma("unroll")                                                   \
            for (int d = 0; d < DD_; d++) {                                     \
                const float p = s_pre[d * BB_ + b];                             \
                pot.x = fmaf(dm[d].x, p, pot.x);                                \
                pot.y = fmaf(dm[d].y, p, pot.y);                                \
                pot.z = fmaf(dm[d].z, p, pot.z);                                \
                pot.w = fmaf(dm[d].w, p, pot.w);                                \
                const float q = s_xd[d * BB_ + b];                              \
                dep.x = fmaf(dm[d].x, q, dep.x);                                \
                dep.y = fmaf(dm[d].y, q, dep.y);                                \
                dep.z = fmaf(dm[d].z, q, dep.z);                                \
                dep.w = fmaf(dm[d].w, q, dep.w);                                \
            }                                                                   \
            const float4 xp = *reinterpret_cast<const float4*>(                 \
                Xpost + (size_t)b * NN_ + o);                                   \
            const float4 xb = *reinterpret_cast<const float4*>(                 \
                xbar_post + (size_t)b * NN_ + o);                               \
            const float4 w = *reinterpret_cast<const float4*>(                  \
                s_w + b * 1024 + t * 4);                                        \
            const size_t idx = (size_t)b * NN_ * NN_ + eo;                      \
            __stcs(reinterpret_cast<float4*>(out + idx), w);                    \
            float4 wn;                                                          \
            wn.x = fminf(fmaxf(fmaf(xp.x * ap.x, pot.x,                         \
                        fmaf(-xb.x * ad.x, dep.x, w.x)), 0.f), 1.f);            \
            wn.y = fminf(fmaxf(fmaf(xp.y * ap.y, pot.y,                         \
                        fmaf(-xb.y * ad.y, dep.y, w.y)), 0.f), 1.f);            \
            wn.z = fminf(fmaxf(fmaf(xp.z * ap.z, pot.z,                         \
                        fmaf(-xb.z * ad.z, dep.z, w.z)), 0.f), 1.f);            \
            wn.w = fminf(fmaxf(fmaf(xp.w * ap.w, pot.w,                         \
                        fmaf(-xb.w * ad.w, dep.w, w.w)), 0.f), 1.f);            \
            __stcs(reinterpret_cast<float4*>(Wnew + idx), wn);                  \
        }                                                                       \
    }

    CP_WAIT(3); PROCESS4(0);
    CP_WAIT(2); PROCESS4(4);
    CP_WAIT(1); PROCESS4(8);
    CP_WAIT(0); PROCESS4(12);
#undef PROCESS4
}

extern "C" void kernel_launch(void* const* d_in, const int* in_sizes, int n_in,
                              void* d_out, int out_size)
{
    const float* Xd        = (const float*)d_in[0]; // (D,B,N)
    const float* Xpost     = (const float*)d_in[1]; // (B,N)
    const float* xbar_pre  = (const float*)d_in[2]; // (D,B,N)
    const float* xbar_post = (const float*)d_in[3]; // (B,N)
    const float* W         = (const float*)d_in[4]; // (B,N,N)
    const float* A_p       = (const float*)d_in[5]; // (N,N)
    const float* A_d       = (const float*)d_in[6]; // (N,N)
    const float* dmap      = (const float*)d_in[7]; // (D,N,N)

    float* out      = (float*)d_out;
    float* Wnew     = out  + (size_t)BB_ * NN_ * NN_;
    float* pre_out  = Wnew + (size_t)BB_ * NN_ * NN_;
    float* post_out = pre_out + (size_t)DD_ * BB_ * NN_;

    const int smem_bytes = SMEM_FLOATS * sizeof(float);   // ~66KB
    static int attr_set = 0;
    if (!attr_set) {
        cudaFuncSetAttribute(stdp_fused,
                             cudaFuncAttributeMaxDynamicSharedMemorySize,
                             smem_bytes);
        attr_set = 1;
    }

    dim3 grid(NN_ / (256 * 4), NN_ + TRACE_BLKS / (NN_ / (256 * 4)));
    stdp_fused<<<grid, 256, smem_bytes>>>(
        Xd, Xpost, xbar_pre, xbar_post, W, A_p, A_d, dmap,
        out, Wnew, pre_out, post_out);
}

// round 5
// speedup vs baseline: 2.8262x; 1.0083x over previous
#include <cuda_runtime.h>
#include <cstdint>

// Problem constants
#define NN_ 2048
#define BB_ 16
#define DD_ 8
#define TRACE_ROWS 16                     // gridDim.x(=2) * 16 = 32 trace blocks

static __device__ __constant__ const float kAlpha = 0.95122945f;
static __device__ __constant__ const float kOneMinusAlpha = 1.0f - 0.95122945f;

// Shared layout (dynamic): W stage [16][1024] floats, then s_pre[8][16], s_xd[8][16]
#define SW_FLOATS   (BB_ * 1024)          // 16384 floats = 64KB
#define SMEM_FLOATS (SW_FLOATS + 2 * DD_ * BB_)

#define CP_ASYNC16(smem_u32, gptr) \
    asm volatile("cp.async.cg.shared.global [%0], [%1], 16;" \
                 :: "r"(smem_u32), "l"(gptr) : "memory")
#define CP_COMMIT() asm volatile("cp.async.commit_group;" ::: "memory")
#define CP_WAIT(n)  asm volatile("cp.async.wait_group %0;" :: "n"(n) : "memory")

__device__ __forceinline__ uint32_t smem_u32(const void* p) {
    return (uint32_t)__cvta_generic_to_shared(p);
}

// ---------------------------------------------------------------------------
// Fused kernel.
//   blockIdx.y <  TRACE_ROWS : trace-update elementwise stream (~3MB),
//                              scheduled FIRST so it hides in wave-0 ramp.
//   blockIdx.y >= TRACE_ROWS : main STDP update, e = blockIdx.y - TRACE_ROWS.
//                              cp.async W pipeline, 8 groups of 2 b-tiles.
// ---------------------------------------------------------------------------
__global__ void __launch_bounds__(256, 2) stdp_fused(
    const float* __restrict__ Xd,        // [D,B,N]
    const float* __restrict__ Xpost,     // [B,N]
    const float* __restrict__ xbar_pre,  // [D,B,N]
    const float* __restrict__ xbar_post, // [B,N]
    const float* __restrict__ W,         // [B,N,N] (b,e,o)
    const float* __restrict__ A_p,       // [N,N]   (e,o)
    const float* __restrict__ A_d,       // [N,N]   (e,o)
    const float* __restrict__ dmap,      // [D,N,N] (d,e,o)
    float* __restrict__ out,             // [B,N,N]
    float* __restrict__ Wnew,            // [B,N,N]
    float* __restrict__ pre_out,         // [D,B,N]
    float* __restrict__ post_out)        // [B,N]
{
    extern __shared__ float sm[];
    float* s_w   = sm;                    // [16][1024]
    float* s_pre = sm + SW_FLOATS;        // [8][16]
    float* s_xd  = s_pre + DD_ * BB_;     // [8][16]

    if (blockIdx.y < TRACE_ROWS) {
        // ---- trace-update stream (runs early, overlapped with main waves) ----
        const int vb = blockIdx.y * gridDim.x + blockIdx.x;   // 0..31
        const int tg = vb * 256 + threadIdx.x;
        const int npre = DD_ * BB_ * NN_ / 4;   // 65536
        const int ntot = npre + BB_ * NN_ / 4;  // 73728
        for (int i = tg; i < ntot; i += TRACE_ROWS * 2 * 256) {
            float4 x, xb;
            if (i < npre) {
                x  = reinterpret_cast<const float4*>(Xd)[i];
                xb = reinterpret_cast<const float4*>(xbar_pre)[i];
            } else {
                x  = reinterpret_cast<const float4*>(Xpost)[i - npre];
                xb = reinterpret_cast<const float4*>(xbar_post)[i - npre];
            }
            float4 r;
            r.x = fmaf(kAlpha, xb.x, kOneMinusAlpha * x.x);
            r.y = fmaf(kAlpha, xb.y, kOneMinusAlpha * x.y);
            r.z = fmaf(kAlpha, xb.z, kOneMinusAlpha * x.z);
            r.w = fmaf(kAlpha, xb.w, kOneMinusAlpha * x.w);
            if (i < npre) reinterpret_cast<float4*>(pre_out)[i] = r;
            else          reinterpret_cast<float4*>(post_out)[i - npre] = r;
        }
        return;
    }

    // ---- main STDP path ----
    const int e = blockIdx.y - TRACE_ROWS;
    const int t = threadIdx.x;
    const int o = blockIdx.x * 1024 + t * 4;
    const size_t eo = (size_t)e * NN_ + o;

    // b-invariant planes FIRST: consumed earliest, get their latency started.
    float4 dm[DD_];
#pragma unroll
    for (int d = 0; d < DD_; d++)
        dm[d] = __ldcs(reinterpret_cast<const float4*>(dmap + (size_t)d * NN_ * NN_ + eo));
    const float4 ap = __ldcs(reinterpret_cast<const float4*>(A_p + eo));
    const float4 ad = __ldcs(reinterpret_cast<const float4*>(A_d + eo));

    // Async-stage all 16 W[b] tiles: 8 commit-groups of 2 for fine-grained
    // release (compute starts after 8KB instead of 16KB; smoother stores).
    const uint32_t swa = smem_u32(s_w + t * 4);
#pragma unroll
    for (int g = 0; g < 8; g++) {
#pragma unroll
        for (int j = 0; j < 2; j++) {
            const int b = g * 2 + j;
            CP_ASYNC16(swa + (uint32_t)b * 4096u, W + (size_t)b * NN_ * NN_ + eo);
        }
        CP_COMMIT();
    }

    // Per-(e) scalars.
    if (t < DD_ * BB_) {
        const int d = t >> 4, b = t & 15;
        s_pre[t] = xbar_pre[((size_t)d * BB_ + b) * NN_ + e];
    } else {
        const int i = t - DD_ * BB_;
        const int d = i >> 4, b = i & 15;
        s_xd[i] = Xd[((size_t)d * BB_ + b) * NN_ + e];
    }
    __syncthreads();

#define PROCESS2(B0)                                                            \
    {                                                                           \
        _Pragma("unroll")                                                       \
        for (int j = 0; j < 2; j++) {                                           \
            const int b = (B0) + j;                                             \
            float4 pot = make_float4(0.f, 0.f, 0.f, 0.f);                       \
            float4 dep = make_float4(0.f, 0.f, 0.f, 0.f);                       \
            _Pragma("unroll")                                                   \
            for (int d = 0; d < DD_; d++) {                                     \
                const float p = s_pre[d * BB_ + b];                             \
                pot.x = fmaf(dm[d].x, p, pot.x);                                \
                pot.y = fmaf(dm[d].y, p, pot.y);                                \
                pot.z = fmaf(dm[d].z, p, pot.z);                                \
                pot.w = fmaf(dm[d].w, p, pot.w);                                \
                const float q = s_xd[d * BB_ + b];                              \
                dep.x = fmaf(dm[d].x, q, dep.x);                                \
                dep.y = fmaf(dm[d].y, q, dep.y);                                \
                dep.z = fmaf(dm[d].z, q, dep.z);                                \
                dep.w = fmaf(dm[d].w, q, dep.w);                                \
            }                                                                   \
            const float4 xp = *reinterpret_cast<const float4*>(                 \
                Xpost + (size_t)b * NN_ + o);                                   \
            const float4 xb = *reinterpret_cast<const float4*>(                 \
                xbar_post + (size_t)b * NN_ + o);                               \
            const float4 w = *reinterpret_cast<const float4*>(                  \
                s_w + b * 1024 + t * 4);                                        \
            const size_t idx = (size_t)b * NN_ * NN_ + eo;                      \
            __stcs(reinterpret_cast<float4*>(out + idx), w);                    \
            float4 wn;                                                          \
            wn.x = fminf(fmaxf(fmaf(xp.x * ap.x, pot.x,                         \
                        fmaf(-xb.x * ad.x, dep.x, w.x)), 0.f), 1.f);            \
            wn.y = fminf(fmaxf(fmaf(xp.y * ap.y, pot.y,                         \
                        fmaf(-xb.y * ad.y, dep.y, w.y)), 0.f), 1.f);            \
            wn.z = fminf(fmaxf(fmaf(xp.z * ap.z, pot.z,                         \
                        fmaf(-xb.z * ad.z, dep.z, w.z)), 0.f), 1.f);            \
            wn.w = fminf(fmaxf(fmaf(xp.w * ap.w, pot.w,                         \
                        fmaf(-xb.w * ad.w, dep.w, w.w)), 0.f), 1.f);            \
            __stcs(reinterpret_cast<float4*>(Wnew + idx), wn);                  \
        }                                                                       \
    }

    CP_WAIT(6); PROCESS2(0);
    CP_WAIT(5); PROCESS2(2);
    CP_WAIT(4); PROCESS2(4);
    CP_WAIT(3); PROCESS2(6);
    CP_WAIT(2); PROCESS2(8);
    CP_WAIT(1); PROCESS2(10);
    CP_WAIT(0); PROCESS2(12);
                PROCESS2(14);
#undef PROCESS2
}

extern "C" void kernel_launch(void* const* d_in, const int* in_sizes, int n_in,
                              void* d_out, int out_size)
{
    const float* Xd        = (const float*)d_in[0]; // (D,B,N)
    const float* Xpost     = (const float*)d_in[1]; // (B,N)
    const float* xbar_pre  = (const float*)d_in[2]; // (D,B,N)
    const float* xbar_post = (const float*)d_in[3]; // (B,N)
    const float* W         = (const float*)d_in[4]; // (B,N,N)
    const float* A_p       = (const float*)d_in[5]; // (N,N)
    const float* A_d       = (const float*)d_in[6]; // (N,N)
    const float* dmap      = (const float*)d_in[7]; // (D,N,N)

    float* out      = (float*)d_out;
    float* Wnew     = out  + (size_t)BB_ * NN_ * NN_;
    float* pre_out  = Wnew + (size_t)BB_ * NN_ * NN_;
    float* post_out = pre_out + (size_t)DD_ * BB_ * NN_;

    const int smem_bytes = SMEM_FLOATS * sizeof(float);   // ~66KB
    static int attr_set = 0;
    if (!attr_set) {
        cudaFuncSetAttribute(stdp_fused,
                             cudaFuncAttributeMaxDynamicSharedMemorySize,
                             smem_bytes);
        attr_set = 1;
    }

    dim3 grid(NN_ / (256 * 4), NN_ + TRACE_ROWS);   // (2, 2064)
    stdp_fused<<<grid, 256, smem_bytes>>>(
        Xd, Xpost, xbar_pre, xbar_post, W, A_p, A_d, dmap,
        out, Wnew, pre_out, post_out);
}